// round 8
// baseline (speedup 1.0000x reference)
#include <cuda_runtime.h>
#include <cuda_bf16.h>
#include <mma.h>
#include <cstdint>

using namespace nvcuda;

#define NN 150000
#define NN2 150016          // padded: 586*256
#define EE 150000
#define GG 128
#define DD 512
#define LL 5

// ---------------- scratch (device globals; no allocation) ----------------
__device__ float g_hx[(size_t)NN * DD];    // linear output
__device__ float g_agg[(size_t)NN * DD];   // aggregation buffer (pre-filled + atomics)
__device__ __nv_bfloat16 g_ahi[(size_t)NN2 * DD];  // split h (zero-init covers pad rows)
__device__ __nv_bfloat16 g_alo[(size_t)NN2 * DD];
__device__ __nv_bfloat16 g_whi[DD * DD];   // W split, [k][n] layout
__device__ __nv_bfloat16 g_wlo[DD * DD];
__device__ float g_vnw[GG * DD];           // vn @ W (fp32)
__device__ float g_deg[NN];
__device__ float g_norm[EE];
__device__ float g_vn[GG * DD];
__device__ float g_vnacc[GG * DD];         // zeroed at load; re-zeroed by k_vng1 after use
__device__ float g_t[GG * 2 * DD];         // vn MLP hidden
__device__ double g_colsum[DD];            // zeroed at load; re-zeroed by k_finalize after use
__device__ double g_colsq[DD];
__device__ float g_mu[DD];
__device__ float g_inv[DD];
__device__ float g_vmu[2 * DD];
__device__ float g_vinv[2 * DD];

__device__ __forceinline__ void bsplit(float a, __nv_bfloat16& hi, __nv_bfloat16& lo) {
    hi = __float2bfloat16(a);
    lo = __float2bfloat16(a - __bfloat162float(hi));
}

// ---------------- fused embed (+ deg init + vn init) ----------------
#define EMB_BLOCKS 75000
__global__ void k_embed(const int* __restrict__ x, const int* __restrict__ nd,
                        const float* __restrict__ te, const float* __restrict__ ae,
                        const float* __restrict__ de, const float* __restrict__ vnw0) {
    if (blockIdx.x >= EMB_BLOCKS) {
        int i = (blockIdx.x - EMB_BLOCKS) * blockDim.x + threadIdx.x;
        if (i < GG * DD) g_vn[i] = vnw0[i & (DD - 1)];
        return;
    }
    int idx = blockIdx.x * blockDim.x + threadIdx.x;   // < NN*128 exactly
    int n = idx >> 7;
    int qq = idx & 127;
    int q = qq * 4;
    if (qq == 0) g_deg[n] = 1.0f;
    int t0 = x[2 * n];
    int a0 = x[2 * n + 1];
    int dp = nd[n]; if (dp > 20) dp = 20;
    float4 v0 = *(const float4*)&te[(size_t)t0 * DD + q];
    float4 v1 = *(const float4*)&ae[(size_t)a0 * DD + q];
    float4 v2 = *(const float4*)&de[(size_t)dp * DD + q];
    float o0 = v0.x + v1.x + v2.x;
    float o1 = v0.y + v1.y + v2.y;
    float o2 = v0.z + v1.z + v2.z;
    float o3 = v0.w + v1.w + v2.w;
    __nv_bfloat16 h0, l0, h1, l1, h2, l2, h3, l3;
    bsplit(o0, h0, l0); bsplit(o1, h1, l1); bsplit(o2, h2, l2); bsplit(o3, h3, l3);
    size_t off = (size_t)n * DD + q;
    *(__nv_bfloat162*)&g_ahi[off] = __nv_bfloat162(h0, h1);
    *(__nv_bfloat162*)&g_ahi[off + 2] = __nv_bfloat162(h2, h3);
    *(__nv_bfloat162*)&g_alo[off] = __nv_bfloat162(l0, l1);
    *(__nv_bfloat162*)&g_alo[off + 2] = __nv_bfloat162(l2, l3);
}

__global__ void k_deg(const int* __restrict__ ei) {
    int e = blockIdx.x * blockDim.x + threadIdx.x;
    if (e < EE) atomicAdd(&g_deg[ei[e]], 1.0f);
}

__global__ void k_norm(const int* __restrict__ ei) {
    int e = blockIdx.x * blockDim.x + threadIdx.x;
    if (e < EE) {
        int r = ei[e];
        int c = ei[EE + e];
        g_norm[e] = rsqrtf(g_deg[r]) * rsqrtf(g_deg[c]);
    }
}

// ---------------- fused per-layer prep: W split + vnW ----------------
__global__ void k_prep(const float* __restrict__ W) {
    if (blockIdx.x < 128) {
        int idx = blockIdx.x * 512 + threadIdx.x;   // < 65536
        int q = idx * 4;
        float4 v = *(const float4*)&W[q];
        __nv_bfloat16 h0, l0, h1, l1, h2, l2, h3, l3;
        bsplit(v.x, h0, l0); bsplit(v.y, h1, l1); bsplit(v.z, h2, l2); bsplit(v.w, h3, l3);
        *(__nv_bfloat162*)&g_whi[q] = __nv_bfloat162(h0, h1);
        *(__nv_bfloat162*)&g_whi[q + 2] = __nv_bfloat162(h2, h3);
        *(__nv_bfloat162*)&g_wlo[q] = __nv_bfloat162(l0, l1);
        *(__nv_bfloat162*)&g_wlo[q + 2] = __nv_bfloat162(l2, l3);
    } else {
        __shared__ float sv[DD];
        int g = blockIdx.x - 128;
        int n = threadIdx.x;   // 512
        sv[n] = g_vn[g * DD + n];
        __syncthreads();
        float acc = 0.f;
        for (int k = 0; k < DD; k++) acc = fmaf(sv[k], W[(size_t)k * DD + n], acc);
        g_vnw[g * DD + n] = acc;
    }
}

// ---------------- GEMM (bf16x3, 256x128 CTA tile, 64x64 warp tile) ----------------
// hx = h@W + vnW[batch] + lb ; agg = relu(hx+cb)/deg
#define BM 256
#define BN 128
#define BK 32
#define NSTG 3

// per-stage layout (bytes):
//   Ah [256][40] bf16 : 0      (20480)
//   Al [256][40] bf16 : 20480  (20480)
//   Bh [32][136] bf16 : 40960  (8704)
//   Bl [32][136] bf16 : 49664  (8704)
#define STG 58368
#define OAL 20480
#define OBH 40960
#define OBL 49664
#define SM_TOT (NSTG * STG)

__device__ __forceinline__ void cpa16(uint32_t dst, const void* src) {
    asm volatile("cp.async.cg.shared.global [%0], [%1], 16;\n" :: "r"(dst), "l"(src));
}
__device__ __forceinline__ void cp_commit() {
    asm volatile("cp.async.commit_group;\n");
}
template<int Nw> __device__ __forceinline__ void cp_wait() {
    asm volatile("cp.async.wait_group %0;\n" :: "n"(Nw));
}

__global__ __launch_bounds__(256, 1) void k_gemm(const int* __restrict__ batch,
                                                 const float* __restrict__ lb,
                                                 const float* __restrict__ cb) {
    extern __shared__ char smc[];
    uint32_t sbase = (uint32_t)__cvta_generic_to_shared(smc);
    int tid = threadIdx.x;
    int warp = tid >> 5;
    int wm = warp >> 1;   // 0..3  (64-row group)
    int wn = warp & 1;    // 0..1  (64-col group)
    int nBase = blockIdx.x * BN;   // x fastest -> col blocks share A slab in L2
    int mBase = blockIdx.y * BM;

    wmma::fragment<wmma::accumulator, 16, 16, 16, float> acc[4][4];
#pragma unroll
    for (int i = 0; i < 4; i++)
#pragma unroll
        for (int j = 0; j < 4; j++) wmma::fill_fragment(acc[i][j], 0.0f);

    auto loadStage = [&](int it) {
        uint32_t base = sbase + (uint32_t)(it % NSTG) * STG;
        int k0 = it * BK;
        // A hi/lo: 2048 chunks of 16B (row = 64B data = 4 chunks, 80B stride)
#pragma unroll
        for (int i = 0; i < 8; i++) {
            int idx = tid + i * 256;     // 0..2047
            int half = idx >> 10;
            int rem = idx & 1023;
            int r = rem >> 2;            // 0..255
            int c = rem & 3;             // 0..3
            const __nv_bfloat16* src =
                (half ? g_alo : g_ahi) + (size_t)(mBase + r) * DD + k0 + c * 8;
            cpa16(base + half * OAL + r * 80 + c * 16, src);
        }
        // B hi/lo: 1024 chunks of 16B (row = 256B data = 16 chunks, 272B stride)
#pragma unroll
        for (int i = 0; i < 4; i++) {
            int idx = tid + i * 256;     // 0..1023
            int half = idx >> 9;
            int rem = idx & 511;
            int r = rem >> 4;            // 0..31
            int c = rem & 15;            // 0..15
            const __nv_bfloat16* src =
                (half ? g_wlo : g_whi) + (size_t)(k0 + r) * DD + nBase + c * 8;
            cpa16(base + OBH + half * 8704 + r * 272 + c * 16, src);
        }
        cp_commit();
    };

    loadStage(0);
    loadStage(1);

    const int NIT = DD / BK;   // 16
    for (int it = 0; it < NIT; it++) {
        if (it < NIT - 1) cp_wait<1>();
        else              cp_wait<0>();
        __syncthreads();
        if (it + 2 < NIT) loadStage(it + 2);

        char* st = smc + (it % NSTG) * STG;
        const __nv_bfloat16* Ah = (const __nv_bfloat16*)st;
        const __nv_bfloat16* Al = (const __nv_bfloat16*)(st + OAL);
        const __nv_bfloat16* Bh = (const __nv_bfloat16*)(st + OBH);
        const __nv_bfloat16* Bl = (const __nv_bfloat16*)(st + OBL);
#pragma unroll
        for (int kk = 0; kk < BK; kk += 16) {
            wmma::fragment<wmma::matrix_a, 16, 16, 16, __nv_bfloat16, wmma::row_major> ah[4], al[4];
            wmma::fragment<wmma::matrix_b, 16, 16, 16, __nv_bfloat16, wmma::row_major> bh[4], bl[4];
#pragma unroll
            for (int i = 0; i < 4; i++) {
                wmma::load_matrix_sync(ah[i], Ah + (wm * 64 + i * 16) * 40 + kk, 40);
                wmma::load_matrix_sync(al[i], Al + (wm * 64 + i * 16) * 40 + kk, 40);
            }
#pragma unroll
            for (int j = 0; j < 4; j++) {
                wmma::load_matrix_sync(bh[j], Bh + kk * 136 + wn * 64 + j * 16, 136);
                wmma::load_matrix_sync(bl[j], Bl + kk * 136 + wn * 64 + j * 16, 136);
            }
#pragma unroll
            for (int i = 0; i < 4; i++)
#pragma unroll
                for (int j = 0; j < 4; j++) {
                    wmma::mma_sync(acc[i][j], ah[i], bl[j], acc[i][j]);
                    wmma::mma_sync(acc[i][j], al[i], bh[j], acc[i][j]);
                    wmma::mma_sync(acc[i][j], ah[i], bh[j], acc[i][j]);
                }
        }
    }
    __syncthreads();

    // epilogue: all warps store 256x128 tile to shared, then fused writeout
    float (*C)[136] = (float(*)[136])smc;   // 256*136*4 = 139264 B < SM_TOT
#pragma unroll
    for (int i = 0; i < 4; i++)
#pragma unroll
        for (int j = 0; j < 4; j++)
            wmma::store_matrix_sync(&C[wm * 64 + i * 16][wn * 64 + j * 16], acc[i][j], 136,
                                    wmma::mem_row_major);
    __syncthreads();
#pragma unroll
    for (int i = 0; i < 32; i++) {
        int idx = tid + i * 256;     // 0..8191 (256 rows x 32 float4)
        int r = idx >> 5;
        int c = (idx & 31) * 4;
        int row = mBase + r;
        if (row < NN) {
            int col = nBase + c;
            float4 v = *(float4*)&C[r][c];
            int bg = batch[row];
            float4 vw = *(const float4*)&g_vnw[bg * DD + col];
            float4 b4 = *(const float4*)&lb[col];
            v.x += vw.x + b4.x; v.y += vw.y + b4.y;
            v.z += vw.z + b4.z; v.w += vw.w + b4.w;
            *(float4*)&g_hx[(size_t)row * DD + col] = v;
            float dg = g_deg[row];
            float4 cb4 = *(const float4*)&cb[col];
            float4 a;
            a.x = fmaxf(v.x + cb4.x, 0.f) / dg;
            a.y = fmaxf(v.y + cb4.y, 0.f) / dg;
            a.z = fmaxf(v.z + cb4.z, 0.f) / dg;
            a.w = fmaxf(v.w + cb4.w, 0.f) / dg;
            *(float4*)&g_agg[(size_t)row * DD + col] = a;
        }
    }
}

// ---------------- message: agg[col] += norm * relu(hx[row] + edge_attr@edge_w + eb) ----------------
__global__ void k_message(const int* __restrict__ ei, const float* __restrict__ ea,
                          const float* __restrict__ ew, const float* __restrict__ eb) {
    int e = blockIdx.x;
    int t = threadIdx.x;       // 0..127
    int d = t * 4;
    int row = ei[e];
    int col = ei[EE + e];
    float nm = g_norm[e];
    float a0 = ea[2 * e];
    float a1 = ea[2 * e + 1];
    float4 w0 = *(const float4*)&ew[d];
    float4 w1 = *(const float4*)&ew[DD + d];
    float4 b4 = *(const float4*)&eb[d];
    float4 h4 = *(const float4*)&g_hx[(size_t)row * DD + d];
    float mx = nm * fmaxf(h4.x + a0 * w0.x + a1 * w1.x + b4.x, 0.f);
    float my = nm * fmaxf(h4.y + a0 * w0.y + a1 * w1.y + b4.y, 0.f);
    float mz = nm * fmaxf(h4.z + a0 * w0.z + a1 * w1.z + b4.z, 0.f);
    float mw = nm * fmaxf(h4.w + a0 * w0.w + a1 * w1.w + b4.w, 0.f);
    float* p = &g_agg[(size_t)col * DD + d];
    asm volatile("red.global.add.v4.f32 [%0], {%1,%2,%3,%4};"
                 :: "l"(p), "f"(mx), "f"(my), "f"(mz), "f"(mw) : "memory");
}

// ---------------- BN stats over columns ----------------
__global__ void k_stats() {
    int c = threadIdx.x;       // 512 threads, column per thread
    int base = blockIdx.x * 256;
    float s = 0.f, s2 = 0.f;
    for (int r = 0; r < 256; r++) {
        int row = base + r;
        if (row >= NN) break;
        float v = g_agg[(size_t)row * DD + c];
        s += v;
        s2 += v * v;
    }
    atomicAdd(&g_colsum[c], (double)s);
    atomicAdd(&g_colsq[c], (double)s2);
}

__global__ void k_finalize() {
    int c = threadIdx.x;
    if (c < DD) {
        double mu = g_colsum[c] / (double)NN;
        double var = g_colsq[c] / (double)NN - mu * mu;
        g_mu[c] = (float)mu;
        g_inv[c] = (float)(1.0 / sqrt(var + 1e-5));
        g_colsum[c] = 0.0;     // re-zero for next layer / next replay
        g_colsq[c] = 0.0;
    }
}

// ---------------- BN apply (+relu + vn pooling + bf16 split, or final output) ----------------
__global__ void k_bnapply(const int* __restrict__ batch, const float* __restrict__ ga,
                          const float* __restrict__ be, float* __restrict__ out, int last) {
    int c = threadIdx.x;
    int base = blockIdx.x * 64;
    float mu = g_mu[c], inv = g_inv[c], g = ga[c], b = be[c];
    if (last) {
        for (int r = 0; r < 64; r++) {
            int row = base + r;
            if (row >= NN) break;
            float v = g_agg[(size_t)row * DD + c];
            out[(size_t)row * DD + c] = (v - mu) * inv * g + b;
        }
        return;
    }
    int cur = -1;
    float acc = 0.f;
    for (int r = 0; r < 64; r++) {
        int row = base + r;
        if (row >= NN) break;
        float v = g_agg[(size_t)row * DD + c];
        v = (v - mu) * inv * g + b;
        v = fmaxf(v, 0.f);
        __nv_bfloat16 hh, ll;
        bsplit(v, hh, ll);
        g_ahi[(size_t)row * DD + c] = hh;
        g_alo[(size_t)row * DD + c] = ll;
        int bg = batch[row];
        if (bg != cur) {
            if (cur >= 0) atomicAdd(&g_vnacc[cur * DD + c], acc);
            cur = bg;
            acc = 0.f;
        }
        acc += v;
    }
    if (cur >= 0) atomicAdd(&g_vnacc[cur * DD + c], acc);
}

// ---------------- virtual-node MLP ----------------
__global__ void k_vng1(const float* __restrict__ W1, const float* __restrict__ b1) {
    __shared__ float sh[2][DD];
    int r0 = blockIdx.x * 2;
    int tid = threadIdx.x;       // 256
#pragma unroll
    for (int i = 0; i < 4; i++) {
        int idx = tid + i * 256;
        int r = idx >> 9;
        int c = idx & 511;
        sh[r][c] = g_vn[(r0 + r) * DD + c] + g_vnacc[(r0 + r) * DD + c];
        g_vnacc[(r0 + r) * DD + c] = 0.0f;   // re-zero for next layer / next replay
    }
    __syncthreads();
    float acc[2][4] = {{0.f, 0.f, 0.f, 0.f}, {0.f, 0.f, 0.f, 0.f}};
    for (int k = 0; k < DD; k++) {
        float s0 = sh[0][k], s1 = sh[1][k];
#pragma unroll
        for (int j = 0; j < 4; j++) {
            float w = W1[(size_t)k * 1024 + tid + j * 256];
            acc[0][j] += s0 * w;
            acc[1][j] += s1 * w;
        }
    }
#pragma unroll
    for (int r = 0; r < 2; r++)
#pragma unroll
        for (int j = 0; j < 4; j++) {
            int col = tid + j * 256;
            g_t[(r0 + r) * 1024 + col] = acc[r][j] + b1[col];
        }
}

__global__ void k_vnstats() {
    int c = threadIdx.x;   // 1024
    float s = 0.f, s2 = 0.f;
    for (int r = 0; r < GG; r++) {
        float v = g_t[r * 1024 + c];
        s += v; s2 += v * v;
    }
    float mu = s / (float)GG;
    float var = s2 / (float)GG - mu * mu;
    g_vmu[c] = mu;
    g_vinv[c] = rsqrtf(var + 1e-5f);
}

__global__ void k_vng2(const float* __restrict__ W2, const float* __restrict__ b2,
                       const float* __restrict__ mg, const float* __restrict__ mbb) {
    __shared__ float sh[2][2 * DD];
    int r0 = blockIdx.x * 2;
    int tid = threadIdx.x;       // 256
#pragma unroll
    for (int i = 0; i < 8; i++) {
        int idx = tid + i * 256;
        int r = idx >> 10;
        int c = idx & 1023;
        float v = g_t[(r0 + r) * 1024 + c];
        v = (v - g_vmu[c]) * g_vinv[c] * mg[c] + mbb[c];
        sh[r][c] = fmaxf(v, 0.f);
    }
    __syncthreads();
    float acc[2][2] = {{0.f, 0.f}, {0.f, 0.f}};
    for (int k = 0; k < 1024; k++) {
        float s0 = sh[0][k], s1 = sh[1][k];
#pragma unroll
        for (int j = 0; j < 2; j++) {
            float w = W2[(size_t)k * DD + tid + j * 256];
            acc[0][j] += s0 * w;
            acc[1][j] += s1 * w;
        }
    }
#pragma unroll
    for (int r = 0; r < 2; r++)
#pragma unroll
        for (int j = 0; j < 2; j++) {
            int col = tid + j * 256;
            g_vn[(r0 + r) * DD + col] = acc[r][j] + b2[col];
        }
}

// ---------------- launcher ----------------
extern "C" void kernel_launch(void* const* d_in, const int* in_sizes, int n_in,
                              void* d_out, int out_size) {
    const int*   x     = (const int*)d_in[0];
    const int*   nd    = (const int*)d_in[1];
    const int*   ei    = (const int*)d_in[2];
    const int*   batch = (const int*)d_in[3];
    const float* ea    = (const float*)d_in[4];
    const float* te    = (const float*)d_in[5];
    const float* ae    = (const float*)d_in[6];
    const float* de    = (const float*)d_in[7];
    const float* vnw   = (const float*)d_in[8];
    const float* lw    = (const float*)d_in[9];
    const float* lb    = (const float*)d_in[10];
    const float* cb    = (const float*)d_in[11];
    const float* ew    = (const float*)d_in[12];
    const float* ebi   = (const float*)d_in[13];
    const float* bng   = (const float*)d_in[14];
    const float* bnb   = (const float*)d_in[15];
    const float* mw1   = (const float*)d_in[16];
    const float* mb1   = (const float*)d_in[17];
    const float* mg    = (const float*)d_in[18];
    const float* mbb   = (const float*)d_in[19];
    const float* mw2   = (const float*)d_in[20];
    const float* mb2   = (const float*)d_in[21];
    float* out = (float*)d_out;

    static int smem_set = 0;
    if (!smem_set) {
        cudaFuncSetAttribute(k_gemm, cudaFuncAttributeMaxDynamicSharedMemorySize, SM_TOT);
        smem_set = 1;
    }

    k_embed<<<EMB_BLOCKS + 256, 256>>>(x, nd, te, ae, de, vnw);
    k_deg<<<(EE + 255) / 256, 256>>>(ei);

    int norm_done = 0;
    for (int l = 0; l < LL; l++) {
        int last = (l == LL - 1) ? 1 : 0;
        k_prep<<<256, 512>>>(lw + (size_t)l * DD * DD);
        // layer-0 GEMM stays the 4th launch so ncu lands on it again
        k_gemm<<<dim3(DD / BN, NN2 / BM), 256, SM_TOT>>>(batch, lb + l * DD, cb + l * DD);
        if (!norm_done) {
            k_norm<<<(EE + 255) / 256, 256>>>(ei);
            norm_done = 1;
        }
        k_message<<<EE, 128>>>(ei, ea, ew + (size_t)l * 2 * DD, ebi + l * DD);
        k_stats<<<(NN + 255) / 256, 512>>>();
        k_finalize<<<1, 512>>>();
        k_bnapply<<<(NN + 63) / 64, 512>>>(batch, bng + l * DD, bnb + l * DD, out, last);
        if (!last) {
            k_vng1<<<GG / 2, 256>>>(mw1 + (size_t)l * DD * 2 * DD, mb1 + l * 2 * DD);
            k_vnstats<<<1, 1024>>>();
            k_vng2<<<GG / 2, 256>>>(mw2 + (size_t)l * 2 * DD * DD, mb2 + l * DD,
                                    mg + l * 2 * DD, mbb + l * 2 * DD);
        }
    }
    (void)in_sizes; (void)n_in; (void)out_size;
}

// round 9
// speedup vs baseline: 1.2892x; 1.2892x over previous
#include <cuda_runtime.h>
#include <cuda_bf16.h>
#include <mma.h>
#include <cstdint>

using namespace nvcuda;

#define NN 150000
#define NN2 150016          // padded to 1172*128
#define EE 150000
#define GG 128
#define DD 512
#define LL 5

// ---------------- scratch (device globals; no allocation) ----------------
__device__ float g_hx[(size_t)NN * DD];    // linear output
__device__ float g_agg[(size_t)NN * DD];   // aggregation buffer (pre-filled + atomics)
__device__ __nv_bfloat16 g_ahi[(size_t)NN2 * DD];  // split h (zero-init covers pad rows)
__device__ __nv_bfloat16 g_alo[(size_t)NN2 * DD];
__device__ __nv_bfloat16 g_whi[DD * DD];   // W split, [k][n] layout
__device__ __nv_bfloat16 g_wlo[DD * DD];
__device__ float g_vnw[GG * DD];           // vn @ W (fp32)
__device__ float g_deg[NN];
__device__ float g_norm[EE];
__device__ float g_vn[GG * DD];
__device__ float g_vnacc[GG * DD];         // zeroed at load; re-zeroed by k_vng1 after use
__device__ float g_t[GG * 2 * DD];         // vn MLP hidden
__device__ double g_colsum[DD];            // zeroed at load; re-zeroed by k_finalize after use
__device__ double g_colsq[DD];
__device__ float g_mu[DD];
__device__ float g_inv[DD];
__device__ float g_vmu[2 * DD];
__device__ float g_vinv[2 * DD];

__device__ __forceinline__ void bsplit(float a, __nv_bfloat16& hi, __nv_bfloat16& lo) {
    hi = __float2bfloat16(a);
    lo = __float2bfloat16(a - __bfloat162float(hi));
}

// ---------------- fused embed (+ deg init + vn init) ----------------
#define EMB_BLOCKS 75000
__global__ void k_embed(const int* __restrict__ x, const int* __restrict__ nd,
                        const float* __restrict__ te, const float* __restrict__ ae,
                        const float* __restrict__ de, const float* __restrict__ vnw0) {
    if (blockIdx.x >= EMB_BLOCKS) {
        int i = (blockIdx.x - EMB_BLOCKS) * blockDim.x + threadIdx.x;
        if (i < GG * DD) g_vn[i] = vnw0[i & (DD - 1)];
        return;
    }
    int idx = blockIdx.x * blockDim.x + threadIdx.x;   // < NN*128 exactly
    int n = idx >> 7;
    int qq = idx & 127;
    int q = qq * 4;
    if (qq == 0) g_deg[n] = 1.0f;
    int t0 = x[2 * n];
    int a0 = x[2 * n + 1];
    int dp = nd[n]; if (dp > 20) dp = 20;
    float4 v0 = *(const float4*)&te[(size_t)t0 * DD + q];
    float4 v1 = *(const float4*)&ae[(size_t)a0 * DD + q];
    float4 v2 = *(const float4*)&de[(size_t)dp * DD + q];
    float o0 = v0.x + v1.x + v2.x;
    float o1 = v0.y + v1.y + v2.y;
    float o2 = v0.z + v1.z + v2.z;
    float o3 = v0.w + v1.w + v2.w;
    __nv_bfloat16 h0, l0, h1, l1, h2, l2, h3, l3;
    bsplit(o0, h0, l0); bsplit(o1, h1, l1); bsplit(o2, h2, l2); bsplit(o3, h3, l3);
    size_t off = (size_t)n * DD + q;
    *(__nv_bfloat162*)&g_ahi[off] = __nv_bfloat162(h0, h1);
    *(__nv_bfloat162*)&g_ahi[off + 2] = __nv_bfloat162(h2, h3);
    *(__nv_bfloat162*)&g_alo[off] = __nv_bfloat162(l0, l1);
    *(__nv_bfloat162*)&g_alo[off + 2] = __nv_bfloat162(l2, l3);
}

__global__ void k_deg(const int* __restrict__ ei) {
    int e = blockIdx.x * blockDim.x + threadIdx.x;
    if (e < EE) atomicAdd(&g_deg[ei[e]], 1.0f);
}

__global__ void k_norm(const int* __restrict__ ei) {
    int e = blockIdx.x * blockDim.x + threadIdx.x;
    if (e < EE) {
        int r = ei[e];
        int c = ei[EE + e];
        g_norm[e] = rsqrtf(g_deg[r]) * rsqrtf(g_deg[c]);
    }
}

// ---------------- fused per-layer prep: W split + vnW ----------------
__global__ void k_prep(const float* __restrict__ W) {
    if (blockIdx.x < 128) {
        int idx = blockIdx.x * 512 + threadIdx.x;   // < 65536
        int q = idx * 4;
        float4 v = *(const float4*)&W[q];
        __nv_bfloat16 h0, l0, h1, l1, h2, l2, h3, l3;
        bsplit(v.x, h0, l0); bsplit(v.y, h1, l1); bsplit(v.z, h2, l2); bsplit(v.w, h3, l3);
        *(__nv_bfloat162*)&g_whi[q] = __nv_bfloat162(h0, h1);
        *(__nv_bfloat162*)&g_whi[q + 2] = __nv_bfloat162(h2, h3);
        *(__nv_bfloat162*)&g_wlo[q] = __nv_bfloat162(l0, l1);
        *(__nv_bfloat162*)&g_wlo[q + 2] = __nv_bfloat162(l2, l3);
    } else {
        __shared__ float sv[DD];
        int g = blockIdx.x - 128;
        int n = threadIdx.x;   // 512
        sv[n] = g_vn[g * DD + n];
        __syncthreads();
        float acc = 0.f;
        for (int k = 0; k < DD; k++) acc = fmaf(sv[k], W[(size_t)k * DD + n], acc);
        g_vnw[g * DD + n] = acc;
    }
}

// ---------------- GEMM (bf16x3, 128x128 tile, register-pressure-shaped inner loop) ----
// hx = h@W + vnW[batch] + lb ; agg = relu(hx+cb)/deg
#define BM 128
#define BN 128
#define BK 32
#define NSTG 3

// per-stage layout (bytes):
//   Ah [128][40] bf16 : 0      (10240)
//   Al [128][40] bf16 : 10240  (10240)
//   Bh [32][136] bf16 : 20480  (8704)
//   Bl [32][136] bf16 : 29184  (8704)
#define STG 37888
#define OAL 10240
#define OBH 20480
#define OBL 29184
#define SM_TOT (NSTG * STG)

__device__ __forceinline__ void cpa16(uint32_t dst, const void* src) {
    asm volatile("cp.async.cg.shared.global [%0], [%1], 16;\n" :: "r"(dst), "l"(src));
}
__device__ __forceinline__ void cp_commit() {
    asm volatile("cp.async.commit_group;\n");
}
template<int Nw> __device__ __forceinline__ void cp_wait() {
    asm volatile("cp.async.wait_group %0;\n" :: "n"(Nw));
}

__global__ __launch_bounds__(256, 2) void k_gemm(const int* __restrict__ batch,
                                                 const float* __restrict__ lb,
                                                 const float* __restrict__ cb) {
    extern __shared__ char smc[];
    uint32_t sbase = (uint32_t)__cvta_generic_to_shared(smc);
    int tid = threadIdx.x;
    int warp = tid >> 5;
    int wm = warp >> 2;   // 0..1
    int wn = warp & 3;    // 0..3
    int nBase = blockIdx.x * BN;   // x fastest -> col blocks share A slab in L2
    int mBase = blockIdx.y * BM;

    wmma::fragment<wmma::accumulator, 16, 16, 16, float> acc[4][2];
#pragma unroll
    for (int i = 0; i < 4; i++)
#pragma unroll
        for (int j = 0; j < 2; j++) wmma::fill_fragment(acc[i][j], 0.0f);

    auto loadStage = [&](int it) {
        uint32_t base = sbase + (uint32_t)(it % NSTG) * STG;
        int k0 = it * BK;
        // A hi/lo: 1024 chunks of 16B (row = 64B = 4 chunks)
#pragma unroll
        for (int i = 0; i < 4; i++) {
            int idx = tid + i * 256;     // 0..1023
            int half = idx >> 9;
            int rem = idx & 511;
            int r = rem >> 2;
            int c = rem & 3;
            const __nv_bfloat16* src =
                (half ? g_alo : g_ahi) + (size_t)(mBase + r) * DD + k0 + c * 8;
            cpa16(base + half * OAL + r * 80 + c * 16, src);
        }
        // B hi/lo: 1024 chunks of 16B
#pragma unroll
        for (int i = 0; i < 4; i++) {
            int idx = tid + i * 256;
            int half = idx >> 9;
            int rem = idx & 511;
            int r = rem >> 4;
            int c = rem & 15;
            const __nv_bfloat16* src =
                (half ? g_wlo : g_whi) + (size_t)(k0 + r) * DD + nBase + c * 8;
            cpa16(base + OBH + half * 8704 + r * 272 + c * 16, src);
        }
        cp_commit();
    };

    loadStage(0);
    loadStage(1);

    const int NIT = DD / BK;   // 16
    for (int it = 0; it < NIT; it++) {
        if (it < NIT - 1) cp_wait<1>();
        else              cp_wait<0>();
        __syncthreads();
        if (it + 2 < NIT) loadStage(it + 2);

        char* st = smc + (it % NSTG) * STG;
        const __nv_bfloat16* Ah = (const __nv_bfloat16*)st;
        const __nv_bfloat16* Al = (const __nv_bfloat16*)(st + OAL);
        const __nv_bfloat16* Bh = (const __nv_bfloat16*)(st + OBH);
        const __nv_bfloat16* Bl = (const __nv_bfloat16*)(st + OBL);
#pragma unroll
        for (int kk = 0; kk < BK; kk += 16) {
            // hoist B fragments for this kk (live: 4 frags = 16 regs)
            wmma::fragment<wmma::matrix_b, 16, 16, 16, __nv_bfloat16, wmma::row_major> bh[2], bl[2];
#pragma unroll
            for (int j = 0; j < 2; j++) {
                wmma::load_matrix_sync(bh[j], Bh + kk * 136 + wn * 32 + j * 16, 136);
                wmma::load_matrix_sync(bl[j], Bl + kk * 136 + wn * 32 + j * 16, 136);
            }
            // stream A fragments one row-block at a time (live: 2 frags = 8 regs)
#pragma unroll
            for (int i = 0; i < 4; i++) {
                wmma::fragment<wmma::matrix_a, 16, 16, 16, __nv_bfloat16, wmma::row_major> ah, al;
                wmma::load_matrix_sync(ah, Ah + (wm * 64 + i * 16) * 40 + kk, 40);
                wmma::load_matrix_sync(al, Al + (wm * 64 + i * 16) * 40 + kk, 40);
                wmma::mma_sync(acc[i][0], ah, bl[0], acc[i][0]);
                wmma::mma_sync(acc[i][1], ah, bl[1], acc[i][1]);
                wmma::mma_sync(acc[i][0], al, bh[0], acc[i][0]);
                wmma::mma_sync(acc[i][1], al, bh[1], acc[i][1]);
                wmma::mma_sync(acc[i][0], ah, bh[0], acc[i][0]);
                wmma::mma_sync(acc[i][1], ah, bh[1], acc[i][1]);
            }
        }
    }
    __syncthreads();

    // epilogue: stage 64 rows at a time through shared, fuse bias + vnW + agg init
    float (*C)[136] = (float(*)[136])smc;
    for (int half = 0; half < 2; half++) {
        if (wm == half) {
#pragma unroll
            for (int i = 0; i < 4; i++)
#pragma unroll
                for (int j = 0; j < 2; j++)
                    wmma::store_matrix_sync(&C[i * 16][wn * 32 + j * 16], acc[i][j], 136,
                                            wmma::mem_row_major);
        }
        __syncthreads();
#pragma unroll
        for (int i = 0; i < 8; i++) {
            int idx = tid + i * 256;     // 0..2047 (64 rows x 32 float4)
            int r = idx >> 5;
            int c = (idx & 31) * 4;
            int row = mBase + half * 64 + r;
            if (row < NN) {
                int col = nBase + c;
                float4 v = *(float4*)&C[r][c];
                int bg = batch[row];
                float4 vw = *(const float4*)&g_vnw[bg * DD + col];
                float4 b4 = *(const float4*)&lb[col];
                v.x += vw.x + b4.x; v.y += vw.y + b4.y;
                v.z += vw.z + b4.z; v.w += vw.w + b4.w;
                *(float4*)&g_hx[(size_t)row * DD + col] = v;
                float dg = g_deg[row];
                float4 cb4 = *(const float4*)&cb[col];
                float4 a;
                a.x = fmaxf(v.x + cb4.x, 0.f) / dg;
                a.y = fmaxf(v.y + cb4.y, 0.f) / dg;
                a.z = fmaxf(v.z + cb4.z, 0.f) / dg;
                a.w = fmaxf(v.w + cb4.w, 0.f) / dg;
                *(float4*)&g_agg[(size_t)row * DD + col] = a;
            }
        }
        __syncthreads();
    }
}

// ---------------- message: agg[col] += norm * relu(hx[row] + edge_attr@edge_w + eb) ----------------
__global__ void k_message(const int* __restrict__ ei, const float* __restrict__ ea,
                          const float* __restrict__ ew, const float* __restrict__ eb) {
    int e = blockIdx.x;
    int t = threadIdx.x;       // 0..127
    int d = t * 4;
    int row = ei[e];
    int col = ei[EE + e];
    float nm = g_norm[e];
    float a0 = ea[2 * e];
    float a1 = ea[2 * e + 1];
    float4 w0 = *(const float4*)&ew[d];
    float4 w1 = *(const float4*)&ew[DD + d];
    float4 b4 = *(const float4*)&eb[d];
    float4 h4 = *(const float4*)&g_hx[(size_t)row * DD + d];
    float mx = nm * fmaxf(h4.x + a0 * w0.x + a1 * w1.x + b4.x, 0.f);
    float my = nm * fmaxf(h4.y + a0 * w0.y + a1 * w1.y + b4.y, 0.f);
    float mz = nm * fmaxf(h4.z + a0 * w0.z + a1 * w1.z + b4.z, 0.f);
    float mw = nm * fmaxf(h4.w + a0 * w0.w + a1 * w1.w + b4.w, 0.f);
    float* p = &g_agg[(size_t)col * DD + d];
    asm volatile("red.global.add.v4.f32 [%0], {%1,%2,%3,%4};"
                 :: "l"(p), "f"(mx), "f"(my), "f"(mz), "f"(mw) : "memory");
}

// ---------------- BN stats over columns ----------------
__global__ void k_stats() {
    int c = threadIdx.x;       // 512 threads, column per thread
    int base = blockIdx.x * 256;
    float s = 0.f, s2 = 0.f;
    for (int r = 0; r < 256; r++) {
        int row = base + r;
        if (row >= NN) break;
        float v = g_agg[(size_t)row * DD + c];
        s += v;
        s2 += v * v;
    }
    atomicAdd(&g_colsum[c], (double)s);
    atomicAdd(&g_colsq[c], (double)s2);
}

__global__ void k_finalize() {
    int c = threadIdx.x;
    if (c < DD) {
        double mu = g_colsum[c] / (double)NN;
        double var = g_colsq[c] / (double)NN - mu * mu;
        g_mu[c] = (float)mu;
        g_inv[c] = (float)(1.0 / sqrt(var + 1e-5));
        g_colsum[c] = 0.0;     // re-zero for next layer / next replay
        g_colsq[c] = 0.0;
    }
}

// ---------------- BN apply (+relu + vn pooling + bf16 split, or final output) ----------------
__global__ void k_bnapply(const int* __restrict__ batch, const float* __restrict__ ga,
                          const float* __restrict__ be, float* __restrict__ out, int last) {
    int c = threadIdx.x;
    int base = blockIdx.x * 64;
    float mu = g_mu[c], inv = g_inv[c], g = ga[c], b = be[c];
    if (last) {
        for (int r = 0; r < 64; r++) {
            int row = base + r;
            if (row >= NN) break;
            float v = g_agg[(size_t)row * DD + c];
            out[(size_t)row * DD + c] = (v - mu) * inv * g + b;
        }
        return;
    }
    int cur = -1;
    float acc = 0.f;
    for (int r = 0; r < 64; r++) {
        int row = base + r;
        if (row >= NN) break;
        float v = g_agg[(size_t)row * DD + c];
        v = (v - mu) * inv * g + b;
        v = fmaxf(v, 0.f);
        __nv_bfloat16 hh, ll;
        bsplit(v, hh, ll);
        g_ahi[(size_t)row * DD + c] = hh;
        g_alo[(size_t)row * DD + c] = ll;
        int bg = batch[row];
        if (bg != cur) {
            if (cur >= 0) atomicAdd(&g_vnacc[cur * DD + c], acc);
            cur = bg;
            acc = 0.f;
        }
        acc += v;
    }
    if (cur >= 0) atomicAdd(&g_vnacc[cur * DD + c], acc);
}

// ---------------- virtual-node MLP ----------------
__global__ void k_vng1(const float* __restrict__ W1, const float* __restrict__ b1) {
    __shared__ float sh[2][DD];
    int r0 = blockIdx.x * 2;
    int tid = threadIdx.x;       // 256
#pragma unroll
    for (int i = 0; i < 4; i++) {
        int idx = tid + i * 256;
        int r = idx >> 9;
        int c = idx & 511;
        sh[r][c] = g_vn[(r0 + r) * DD + c] + g_vnacc[(r0 + r) * DD + c];
        g_vnacc[(r0 + r) * DD + c] = 0.0f;   // re-zero for next layer / next replay
    }
    __syncthreads();
    float acc[2][4] = {{0.f, 0.f, 0.f, 0.f}, {0.f, 0.f, 0.f, 0.f}};
    for (int k = 0; k < DD; k++) {
        float s0 = sh[0][k], s1 = sh[1][k];
#pragma unroll
        for (int j = 0; j < 4; j++) {
            float w = W1[(size_t)k * 1024 + tid + j * 256];
            acc[0][j] += s0 * w;
            acc[1][j] += s1 * w;
        }
    }
#pragma unroll
    for (int r = 0; r < 2; r++)
#pragma unroll
        for (int j = 0; j < 4; j++) {
            int col = tid + j * 256;
            g_t[(r0 + r) * 1024 + col] = acc[r][j] + b1[col];
        }
}

__global__ void k_vnstats() {
    int c = threadIdx.x;   // 1024
    float s = 0.f, s2 = 0.f;
    for (int r = 0; r < GG; r++) {
        float v = g_t[r * 1024 + c];
        s += v; s2 += v * v;
    }
    float mu = s / (float)GG;
    float var = s2 / (float)GG - mu * mu;
    g_vmu[c] = mu;
    g_vinv[c] = rsqrtf(var + 1e-5f);
}

__global__ void k_vng2(const float* __restrict__ W2, const float* __restrict__ b2,
                       const float* __restrict__ mg, const float* __restrict__ mbb) {
    __shared__ float sh[2][2 * DD];
    int r0 = blockIdx.x * 2;
    int tid = threadIdx.x;       // 256
#pragma unroll
    for (int i = 0; i < 8; i++) {
        int idx = tid + i * 256;
        int r = idx >> 10;
        int c = idx & 1023;
        float v = g_t[(r0 + r) * 1024 + c];
        v = (v - g_vmu[c]) * g_vinv[c] * mg[c] + mbb[c];
        sh[r][c] = fmaxf(v, 0.f);
    }
    __syncthreads();
    float acc[2][2] = {{0.f, 0.f}, {0.f, 0.f}};
    for (int k = 0; k < 1024; k++) {
        float s0 = sh[0][k], s1 = sh[1][k];
#pragma unroll
        for (int j = 0; j < 2; j++) {
            float w = W2[(size_t)k * DD + tid + j * 256];
            acc[0][j] += s0 * w;
            acc[1][j] += s1 * w;
        }
    }
#pragma unroll
    for (int r = 0; r < 2; r++)
#pragma unroll
        for (int j = 0; j < 2; j++) {
            int col = tid + j * 256;
            g_vn[(r0 + r) * DD + col] = acc[r][j] + b2[col];
        }
}

// ---------------- launcher ----------------
extern "C" void kernel_launch(void* const* d_in, const int* in_sizes, int n_in,
                              void* d_out, int out_size) {
    const int*   x     = (const int*)d_in[0];
    const int*   nd    = (const int*)d_in[1];
    const int*   ei    = (const int*)d_in[2];
    const int*   batch = (const int*)d_in[3];
    const float* ea    = (const float*)d_in[4];
    const float* te    = (const float*)d_in[5];
    const float* ae    = (const float*)d_in[6];
    const float* de    = (const float*)d_in[7];
    const float* vnw   = (const float*)d_in[8];
    const float* lw    = (const float*)d_in[9];
    const float* lb    = (const float*)d_in[10];
    const float* cb    = (const float*)d_in[11];
    const float* ew    = (const float*)d_in[12];
    const float* ebi   = (const float*)d_in[13];
    const float* bng   = (const float*)d_in[14];
    const float* bnb   = (const float*)d_in[15];
    const float* mw1   = (const float*)d_in[16];
    const float* mb1   = (const float*)d_in[17];
    const float* mg    = (const float*)d_in[18];
    const float* mbb   = (const float*)d_in[19];
    const float* mw2   = (const float*)d_in[20];
    const float* mb2   = (const float*)d_in[21];
    float* out = (float*)d_out;

    static int smem_set = 0;
    if (!smem_set) {
        cudaFuncSetAttribute(k_gemm, cudaFuncAttributeMaxDynamicSharedMemorySize, SM_TOT);
        smem_set = 1;
    }

    k_embed<<<EMB_BLOCKS + 256, 256>>>(x, nd, te, ae, de, vnw);
    k_deg<<<(EE + 255) / 256, 256>>>(ei);

    int norm_done = 0;
    for (int l = 0; l < LL; l++) {
        int last = (l == LL - 1) ? 1 : 0;
        k_prep<<<256, 512>>>(lw + (size_t)l * DD * DD);
        // layer-0 GEMM stays the 4th launch so ncu lands on it again
        k_gemm<<<dim3(DD / BN, NN2 / BM), 256, SM_TOT>>>(batch, lb + l * DD, cb + l * DD);
        if (!norm_done) {
            k_norm<<<(EE + 255) / 256, 256>>>(ei);
            norm_done = 1;
        }
        k_message<<<EE, 128>>>(ei, ea, ew + (size_t)l * 2 * DD, ebi + l * DD);
        k_stats<<<(NN + 255) / 256, 512>>>();
        k_finalize<<<1, 512>>>();
        k_bnapply<<<(NN + 63) / 64, 512>>>(batch, bng + l * DD, bnb + l * DD, out, last);
        if (!last) {
            k_vng1<<<GG / 2, 256>>>(mw1 + (size_t)l * DD * 2 * DD, mb1 + l * 2 * DD);
            k_vnstats<<<1, 1024>>>();
            k_vng2<<<GG / 2, 256>>>(mw2 + (size_t)l * 2 * DD * DD, mb2 + l * DD,
                                    mg + l * 2 * DD, mbb + l * 2 * DD);
        }
    }
    (void)in_sizes; (void)n_in; (void)out_size;
}

// round 10
// speedup vs baseline: 1.3075x; 1.0143x over previous
#include <cuda_runtime.h>
#include <cuda_bf16.h>
#include <mma.h>
#include <cstdint>

using namespace nvcuda;

#define NN 150000
#define NN2 150016          // padded to 1172*128
#define EE 150000
#define GG 128
#define DD 512
#define LL 5

// ---------------- scratch (device globals; no allocation) ----------------
__device__ float g_hx[(size_t)NN * DD];    // linear output
__device__ float g_agg[(size_t)NN * DD];   // aggregation buffer (pre-filled + atomics)
__device__ __nv_bfloat16 g_ahi[(size_t)NN2 * DD];  // split h (zero-init covers pad rows)
__device__ __nv_bfloat16 g_alo[(size_t)NN2 * DD];
__device__ __nv_bfloat16 g_whi[DD * DD];   // W split, [k][n] layout
__device__ __nv_bfloat16 g_wlo[DD * DD];
__device__ float g_vnw[GG * DD];           // vn @ W (fp32)
__device__ float g_deg[NN];
__device__ float g_norm[EE];
__device__ float g_vn[GG * DD];
__device__ float g_vnacc[GG * DD];         // zeroed at load; re-zeroed by k_vng1 after use
__device__ float g_t[GG * 2 * DD];         // vn MLP hidden
__device__ double g_colsum[DD];            // zeroed at load; re-zeroed by k_finalize after use
__device__ double g_colsq[DD];
__device__ float g_mu[DD];
__device__ float g_inv[DD];
__device__ float g_vmu[2 * DD];
__device__ float g_vinv[2 * DD];

__device__ __forceinline__ void bsplit(float a, __nv_bfloat16& hi, __nv_bfloat16& lo) {
    hi = __float2bfloat16(a);
    lo = __float2bfloat16(a - __bfloat162float(hi));
}

// ---------------- fused embed (+ deg init + vn init) ----------------
#define EMB_BLOCKS 75000
__global__ void k_embed(const int* __restrict__ x, const int* __restrict__ nd,
                        const float* __restrict__ te, const float* __restrict__ ae,
                        const float* __restrict__ de, const float* __restrict__ vnw0) {
    if (blockIdx.x >= EMB_BLOCKS) {
        int i = (blockIdx.x - EMB_BLOCKS) * blockDim.x + threadIdx.x;
        if (i < GG * DD) g_vn[i] = vnw0[i & (DD - 1)];
        return;
    }
    int idx = blockIdx.x * blockDim.x + threadIdx.x;   // < NN*128 exactly
    int n = idx >> 7;
    int qq = idx & 127;
    int q = qq * 4;
    if (qq == 0) g_deg[n] = 1.0f;
    int t0 = x[2 * n];
    int a0 = x[2 * n + 1];
    int dp = nd[n]; if (dp > 20) dp = 20;
    float4 v0 = *(const float4*)&te[(size_t)t0 * DD + q];
    float4 v1 = *(const float4*)&ae[(size_t)a0 * DD + q];
    float4 v2 = *(const float4*)&de[(size_t)dp * DD + q];
    float o0 = v0.x + v1.x + v2.x;
    float o1 = v0.y + v1.y + v2.y;
    float o2 = v0.z + v1.z + v2.z;
    float o3 = v0.w + v1.w + v2.w;
    __nv_bfloat16 h0, l0, h1, l1, h2, l2, h3, l3;
    bsplit(o0, h0, l0); bsplit(o1, h1, l1); bsplit(o2, h2, l2); bsplit(o3, h3, l3);
    size_t off = (size_t)n * DD + q;
    *(__nv_bfloat162*)&g_ahi[off] = __nv_bfloat162(h0, h1);
    *(__nv_bfloat162*)&g_ahi[off + 2] = __nv_bfloat162(h2, h3);
    *(__nv_bfloat162*)&g_alo[off] = __nv_bfloat162(l0, l1);
    *(__nv_bfloat162*)&g_alo[off + 2] = __nv_bfloat162(l2, l3);
}

__global__ void k_deg(const int* __restrict__ ei) {
    int e = blockIdx.x * blockDim.x + threadIdx.x;
    if (e < EE) atomicAdd(&g_deg[ei[e]], 1.0f);
}

__global__ void k_norm(const int* __restrict__ ei) {
    int e = blockIdx.x * blockDim.x + threadIdx.x;
    if (e < EE) {
        int r = ei[e];
        int c = ei[EE + e];
        g_norm[e] = rsqrtf(g_deg[r]) * rsqrtf(g_deg[c]);
    }
}

// ---------------- fused per-layer prep: W split + vnW ----------------
__global__ void k_prep(const float* __restrict__ W) {
    if (blockIdx.x < 128) {
        int idx = blockIdx.x * 512 + threadIdx.x;   // < 65536
        int q = idx * 4;
        float4 v = *(const float4*)&W[q];
        __nv_bfloat16 h0, l0, h1, l1, h2, l2, h3, l3;
        bsplit(v.x, h0, l0); bsplit(v.y, h1, l1); bsplit(v.z, h2, l2); bsplit(v.w, h3, l3);
        *(__nv_bfloat162*)&g_whi[q] = __nv_bfloat162(h0, h1);
        *(__nv_bfloat162*)&g_whi[q + 2] = __nv_bfloat162(h2, h3);
        *(__nv_bfloat162*)&g_wlo[q] = __nv_bfloat162(l0, l1);
        *(__nv_bfloat162*)&g_wlo[q + 2] = __nv_bfloat162(l2, l3);
    } else {
        __shared__ float sv[DD];
        int g = blockIdx.x - 128;
        int n = threadIdx.x;   // 512
        sv[n] = g_vn[g * DD + n];
        __syncthreads();
        float acc = 0.f;
        for (int k = 0; k < DD; k++) acc = fmaf(sv[k], W[(size_t)k * DD + n], acc);
        g_vnw[g * DD + n] = acc;
    }
}

// ---------------- GEMM (bf16x3, 128x128 tile, A-fragment software pipeline) ----
// hx = h@W + vnW[batch] + lb ; agg = relu(hx+cb)/deg
#define BM 128
#define BN 128
#define BK 32
#define NSTG 3

// per-stage layout (bytes):
//   Ah [128][40] bf16 : 0      (10240)
//   Al [128][40] bf16 : 10240  (10240)
//   Bh [32][136] bf16 : 20480  (8704)
//   Bl [32][136] bf16 : 29184  (8704)
#define STG 37888
#define OAL 10240
#define OBH 20480
#define OBL 29184
#define SM_TOT (NSTG * STG)

__device__ __forceinline__ void cpa16(uint32_t dst, const void* src) {
    asm volatile("cp.async.cg.shared.global [%0], [%1], 16;\n" :: "r"(dst), "l"(src));
}
__device__ __forceinline__ void cp_commit() {
    asm volatile("cp.async.commit_group;\n");
}
template<int Nw> __device__ __forceinline__ void cp_wait() {
    asm volatile("cp.async.wait_group %0;\n" :: "n"(Nw));
}

__global__ __launch_bounds__(256, 2) void k_gemm(const int* __restrict__ batch,
                                                 const float* __restrict__ lb,
                                                 const float* __restrict__ cb) {
    extern __shared__ char smc[];
    uint32_t sbase = (uint32_t)__cvta_generic_to_shared(smc);
    int tid = threadIdx.x;
    int warp = tid >> 5;
    int wm = warp >> 2;   // 0..1
    int wn = warp & 3;    // 0..3
    int nBase = blockIdx.x * BN;   // x fastest -> col blocks share A slab in L2
    int mBase = blockIdx.y * BM;

    wmma::fragment<wmma::accumulator, 16, 16, 16, float> acc[4][2];
#pragma unroll
    for (int i = 0; i < 4; i++)
#pragma unroll
        for (int j = 0; j < 2; j++) wmma::fill_fragment(acc[i][j], 0.0f);

    auto loadStage = [&](int it) {
        uint32_t base = sbase + (uint32_t)(it % NSTG) * STG;
        int k0 = it * BK;
        // A hi/lo: 1024 chunks of 16B (row = 64B = 4 chunks)
#pragma unroll
        for (int i = 0; i < 4; i++) {
            int idx = tid + i * 256;     // 0..1023
            int half = idx >> 9;
            int rem = idx & 511;
            int r = rem >> 2;
            int c = rem & 3;
            const __nv_bfloat16* src =
                (half ? g_alo : g_ahi) + (size_t)(mBase + r) * DD + k0 + c * 8;
            cpa16(base + half * OAL + r * 80 + c * 16, src);
        }
        // B hi/lo: 1024 chunks of 16B
#pragma unroll
        for (int i = 0; i < 4; i++) {
            int idx = tid + i * 256;
            int half = idx >> 9;
            int rem = idx & 511;
            int r = rem >> 4;
            int c = rem & 15;
            const __nv_bfloat16* src =
                (half ? g_wlo : g_whi) + (size_t)(k0 + r) * DD + nBase + c * 8;
            cpa16(base + OBH + half * 8704 + r * 272 + c * 16, src);
        }
        cp_commit();
    };

    loadStage(0);
    loadStage(1);

    const int NIT = DD / BK;   // 16
    for (int it = 0; it < NIT; it++) {
        if (it < NIT - 1) cp_wait<1>();
        else              cp_wait<0>();
        __syncthreads();
        if (it + 2 < NIT) loadStage(it + 2);

        char* st = smc + (it % NSTG) * STG;
        const __nv_bfloat16* Ah = (const __nv_bfloat16*)st;
        const __nv_bfloat16* Al = (const __nv_bfloat16*)(st + OAL);
        const __nv_bfloat16* Bh = (const __nv_bfloat16*)(st + OBH);
        const __nv_bfloat16* Bl = (const __nv_bfloat16*)(st + OBL);
#pragma unroll
        for (int kk = 0; kk < BK; kk += 16) {
            // hoist B fragments for this kk (live: 4 frags = 16 regs)
            wmma::fragment<wmma::matrix_b, 16, 16, 16, __nv_bfloat16, wmma::row_major> bh[2], bl[2];
#pragma unroll
            for (int j = 0; j < 2; j++) {
                wmma::load_matrix_sync(bh[j], Bh + kk * 136 + wn * 32 + j * 16, 136);
                wmma::load_matrix_sync(bl[j], Bl + kk * 136 + wn * 32 + j * 16, 136);
            }
            // A-fragment rotation: prefetch row-block i+1 while MMAing i
            wmma::fragment<wmma::matrix_a, 16, 16, 16, __nv_bfloat16, wmma::row_major> ah[2], al[2];
            wmma::load_matrix_sync(ah[0], Ah + (wm * 64) * 40 + kk, 40);
            wmma::load_matrix_sync(al[0], Al + (wm * 64) * 40 + kk, 40);
#pragma unroll
            for (int i = 0; i < 4; i++) {
                int cur = i & 1, nxt = cur ^ 1;
                if (i < 3) {
                    wmma::load_matrix_sync(ah[nxt], Ah + (wm * 64 + (i + 1) * 16) * 40 + kk, 40);
                    wmma::load_matrix_sync(al[nxt], Al + (wm * 64 + (i + 1) * 16) * 40 + kk, 40);
                }
                wmma::mma_sync(acc[i][0], ah[cur], bl[0], acc[i][0]);
                wmma::mma_sync(acc[i][1], ah[cur], bl[1], acc[i][1]);
                wmma::mma_sync(acc[i][0], al[cur], bh[0], acc[i][0]);
                wmma::mma_sync(acc[i][1], al[cur], bh[1], acc[i][1]);
                wmma::mma_sync(acc[i][0], ah[cur], bh[0], acc[i][0]);
                wmma::mma_sync(acc[i][1], ah[cur], bh[1], acc[i][1]);
            }
        }
    }
    __syncthreads();

    // epilogue: stage 64 rows at a time through shared, fuse bias + vnW + agg init
    float (*C)[136] = (float(*)[136])smc;
    for (int half = 0; half < 2; half++) {
        if (wm == half) {
#pragma unroll
            for (int i = 0; i < 4; i++)
#pragma unroll
                for (int j = 0; j < 2; j++)
                    wmma::store_matrix_sync(&C[i * 16][wn * 32 + j * 16], acc[i][j], 136,
                                            wmma::mem_row_major);
        }
        __syncthreads();
#pragma unroll
        for (int i = 0; i < 8; i++) {
            int idx = tid + i * 256;     // 0..2047 (64 rows x 32 float4)
            int r = idx >> 5;
            int c = (idx & 31) * 4;
            int row = mBase + half * 64 + r;
            if (row < NN) {
                int col = nBase + c;
                float4 v = *(float4*)&C[r][c];
                int bg = batch[row];
                float4 vw = *(const float4*)&g_vnw[bg * DD + col];
                float4 b4 = *(const float4*)&lb[col];
                v.x += vw.x + b4.x; v.y += vw.y + b4.y;
                v.z += vw.z + b4.z; v.w += vw.w + b4.w;
                *(float4*)&g_hx[(size_t)row * DD + col] = v;
                float dg = g_deg[row];
                float4 cb4 = *(const float4*)&cb[col];
                float4 a;
                a.x = fmaxf(v.x + cb4.x, 0.f) / dg;
                a.y = fmaxf(v.y + cb4.y, 0.f) / dg;
                a.z = fmaxf(v.z + cb4.z, 0.f) / dg;
                a.w = fmaxf(v.w + cb4.w, 0.f) / dg;
                *(float4*)&g_agg[(size_t)row * DD + col] = a;
            }
        }
        __syncthreads();
    }
}

// ---------------- message: agg[col] += norm * relu(hx[row] + edge_attr@edge_w + eb) ----------------
// 2 edges per block (256 threads)
__global__ void k_message(const int* __restrict__ ei, const float* __restrict__ ea,
                          const float* __restrict__ ew, const float* __restrict__ eb) {
    int e = blockIdx.x * 2 + (threadIdx.x >> 7);
    int t = threadIdx.x & 127;
    int d = t * 4;
    int row = ei[e];
    int col = ei[EE + e];
    float nm = g_norm[e];
    float a0 = ea[2 * e];
    float a1 = ea[2 * e + 1];
    float4 w0 = *(const float4*)&ew[d];
    float4 w1 = *(const float4*)&ew[DD + d];
    float4 b4 = *(const float4*)&eb[d];
    float4 h4 = *(const float4*)&g_hx[(size_t)row * DD + d];
    float mx = nm * fmaxf(h4.x + a0 * w0.x + a1 * w1.x + b4.x, 0.f);
    float my = nm * fmaxf(h4.y + a0 * w0.y + a1 * w1.y + b4.y, 0.f);
    float mz = nm * fmaxf(h4.z + a0 * w0.z + a1 * w1.z + b4.z, 0.f);
    float mw = nm * fmaxf(h4.w + a0 * w0.w + a1 * w1.w + b4.w, 0.f);
    float* p = &g_agg[(size_t)col * DD + d];
    asm volatile("red.global.add.v4.f32 [%0], {%1,%2,%3,%4};"
                 :: "l"(p), "f"(mx), "f"(my), "f"(mz), "f"(mw) : "memory");
}

// ---------------- BN stats over columns ----------------
__global__ void k_stats() {
    int c = threadIdx.x;       // 512 threads, column per thread
    int base = blockIdx.x * 256;
    float s = 0.f, s2 = 0.f;
    for (int r = 0; r < 256; r++) {
        int row = base + r;
        if (row >= NN) break;
        float v = g_agg[(size_t)row * DD + c];
        s += v;
        s2 += v * v;
    }
    atomicAdd(&g_colsum[c], (double)s);
    atomicAdd(&g_colsq[c], (double)s2);
}

__global__ void k_finalize() {
    int c = threadIdx.x;
    if (c < DD) {
        double mu = g_colsum[c] / (double)NN;
        double var = g_colsq[c] / (double)NN - mu * mu;
        g_mu[c] = (float)mu;
        g_inv[c] = (float)(1.0 / sqrt(var + 1e-5));
        g_colsum[c] = 0.0;     // re-zero for next layer / next replay
        g_colsq[c] = 0.0;
    }
}

// ---------------- BN apply (+relu + vn pooling + bf16 split, or final output) ----------------
__global__ void k_bnapply(const int* __restrict__ batch, const float* __restrict__ ga,
                          const float* __restrict__ be, float* __restrict__ out, int last) {
    int c = threadIdx.x;
    int base = blockIdx.x * 64;
    float mu = g_mu[c], inv = g_inv[c], g = ga[c], b = be[c];
    if (last) {
        for (int r = 0; r < 64; r++) {
            int row = base + r;
            if (row >= NN) break;
            float v = g_agg[(size_t)row * DD + c];
            out[(size_t)row * DD + c] = (v - mu) * inv * g + b;
        }
        return;
    }
    int cur = -1;
    float acc = 0.f;
    for (int r = 0; r < 64; r++) {
        int row = base + r;
        if (row >= NN) break;
        float v = g_agg[(size_t)row * DD + c];
        v = (v - mu) * inv * g + b;
        v = fmaxf(v, 0.f);
        __nv_bfloat16 hh, ll;
        bsplit(v, hh, ll);
        g_ahi[(size_t)row * DD + c] = hh;
        g_alo[(size_t)row * DD + c] = ll;
        int bg = batch[row];
        if (bg != cur) {
            if (cur >= 0) atomicAdd(&g_vnacc[cur * DD + c], acc);
            cur = bg;
            acc = 0.f;
        }
        acc += v;
    }
    if (cur >= 0) atomicAdd(&g_vnacc[cur * DD + c], acc);
}

// ---------------- virtual-node MLP ----------------
__global__ void k_vng1(const float* __restrict__ W1, const float* __restrict__ b1) {
    __shared__ float sh[2][DD];
    int r0 = blockIdx.x * 2;
    int tid = threadIdx.x;       // 256
#pragma unroll
    for (int i = 0; i < 4; i++) {
        int idx = tid + i * 256;
        int r = idx >> 9;
        int c = idx & 511;
        sh[r][c] = g_vn[(r0 + r) * DD + c] + g_vnacc[(r0 + r) * DD + c];
        g_vnacc[(r0 + r) * DD + c] = 0.0f;   // re-zero for next layer / next replay
    }
    __syncthreads();
    float acc[2][4] = {{0.f, 0.f, 0.f, 0.f}, {0.f, 0.f, 0.f, 0.f}};
    for (int k = 0; k < DD; k++) {
        float s0 = sh[0][k], s1 = sh[1][k];
#pragma unroll
        for (int j = 0; j < 4; j++) {
            float w = W1[(size_t)k * 1024 + tid + j * 256];
            acc[0][j] += s0 * w;
            acc[1][j] += s1 * w;
        }
    }
#pragma unroll
    for (int r = 0; r < 2; r++)
#pragma unroll
        for (int j = 0; j < 4; j++) {
            int col = tid + j * 256;
            g_t[(r0 + r) * 1024 + col] = acc[r][j] + b1[col];
        }
}

__global__ void k_vnstats() {
    int c = threadIdx.x;   // 1024
    float s = 0.f, s2 = 0.f;
    for (int r = 0; r < GG; r++) {
        float v = g_t[r * 1024 + c];
        s += v; s2 += v * v;
    }
    float mu = s / (float)GG;
    float var = s2 / (float)GG - mu * mu;
    g_vmu[c] = mu;
    g_vinv[c] = rsqrtf(var + 1e-5f);
}

__global__ void k_vng2(const float* __restrict__ W2, const float* __restrict__ b2,
                       const float* __restrict__ mg, const float* __restrict__ mbb) {
    __shared__ float sh[2][2 * DD];
    int r0 = blockIdx.x * 2;
    int tid = threadIdx.x;       // 256
#pragma unroll
    for (int i = 0; i < 8; i++) {
        int idx = tid + i * 256;
        int r = idx >> 10;
        int c = idx & 1023;
        float v = g_t[(r0 + r) * 1024 + c];
        v = (v - g_vmu[c]) * g_vinv[c] * mg[c] + mbb[c];
        sh[r][c] = fmaxf(v, 0.f);
    }
    __syncthreads();
    float acc[2][2] = {{0.f, 0.f}, {0.f, 0.f}};
    for (int k = 0; k < 1024; k++) {
        float s0 = sh[0][k], s1 = sh[1][k];
#pragma unroll
        for (int j = 0; j < 2; j++) {
            float w = W2[(size_t)k * DD + tid + j * 256];
            acc[0][j] += s0 * w;
            acc[1][j] += s1 * w;
        }
    }
#pragma unroll
    for (int r = 0; r < 2; r++)
#pragma unroll
        for (int j = 0; j < 2; j++) {
            int col = tid + j * 256;
            g_vn[(r0 + r) * DD + col] = acc[r][j] + b2[col];
        }
}

// ---------------- launcher ----------------
extern "C" void kernel_launch(void* const* d_in, const int* in_sizes, int n_in,
                              void* d_out, int out_size) {
    const int*   x     = (const int*)d_in[0];
    const int*   nd    = (const int*)d_in[1];
    const int*   ei    = (const int*)d_in[2];
    const int*   batch = (const int*)d_in[3];
    const float* ea    = (const float*)d_in[4];
    const float* te    = (const float*)d_in[5];
    const float* ae    = (const float*)d_in[6];
    const float* de    = (const float*)d_in[7];
    const float* vnw   = (const float*)d_in[8];
    const float* lw    = (const float*)d_in[9];
    const float* lb    = (const float*)d_in[10];
    const float* cb    = (const float*)d_in[11];
    const float* ew    = (const float*)d_in[12];
    const float* ebi   = (const float*)d_in[13];
    const float* bng   = (const float*)d_in[14];
    const float* bnb   = (const float*)d_in[15];
    const float* mw1   = (const float*)d_in[16];
    const float* mb1   = (const float*)d_in[17];
    const float* mg    = (const float*)d_in[18];
    const float* mbb   = (const float*)d_in[19];
    const float* mw2   = (const float*)d_in[20];
    const float* mb2   = (const float*)d_in[21];
    float* out = (float*)d_out;

    static int smem_set = 0;
    if (!smem_set) {
        cudaFuncSetAttribute(k_gemm, cudaFuncAttributeMaxDynamicSharedMemorySize, SM_TOT);
        smem_set = 1;
    }

    k_embed<<<EMB_BLOCKS + 256, 256>>>(x, nd, te, ae, de, vnw);
    k_deg<<<(EE + 255) / 256, 256>>>(ei);

    int norm_done = 0;
    for (int l = 0; l < LL; l++) {
        int last = (l == LL - 1) ? 1 : 0;
        k_prep<<<256, 512>>>(lw + (size_t)l * DD * DD);
        // layer-0 GEMM stays the 4th launch so ncu lands on it again
        k_gemm<<<dim3(DD / BN, NN2 / BM), 256, SM_TOT>>>(batch, lb + l * DD, cb + l * DD);
        if (!norm_done) {
            k_norm<<<(EE + 255) / 256, 256>>>(ei);
            norm_done = 1;
        }
        k_message<<<EE / 2, 256>>>(ei, ea, ew + (size_t)l * 2 * DD, ebi + l * DD);
        k_stats<<<(NN + 255) / 256, 512>>>();
        k_finalize<<<1, 512>>>();
        k_bnapply<<<(NN + 63) / 64, 512>>>(batch, bng + l * DD, bnb + l * DD, out, last);
        if (!last) {
            k_vng1<<<GG / 2, 256>>>(mw1 + (size_t)l * DD * 2 * DD, mb1 + l * 2 * DD);
            k_vnstats<<<1, 1024>>>();
            k_vng2<<<GG / 2, 256>>>(mw2 + (size_t)l * 2 * DD * DD, mb2 + l * DD,
                                    mg + l * 2 * DD, mbb + l * 2 * DD);
        }
    }
    (void)in_sizes; (void)n_in; (void)out_size;
}